// round 9
// baseline (speedup 1.0000x reference)
#include <cuda_runtime.h>
#include <cuda_bf16.h>
#include <mma.h>
#include <cuda_pipeline.h>
#include <float.h>
#include <math.h>
#include <stdint.h>

using namespace nvcuda;

// Problem constants
#define BB 2
#define NN 2048
#define DD 1024
#define HH 16
#define DH 64
#define DH3 (3*DH)           // 192
#define MROWS (BB*NN)        // 4096
#define QKVC (3*HH*DH)       // 3072
#define OUTC (HH*DH)         // 1024
#define K3 (3*DD)            // 3072

// GEMM tile config
#define GSTRIDE 72
#define STAGE_ELEMS (2 * 128 * GSTRIDE)
#define B_OFF (128 * GSTRIDE)
#define GEMM_SMEM (2 * STAGE_ELEMS * 2)

// Flash config: BM=64 q rows, BN=32 kv cols, 2 blocks/SM.
#define FBN 32
#define FQ_STRIDE 200        // q/k rows: 192 data + pad (400B, conflict-free)
#define FV_STRIDE 72         // v rows: 64 data + pad (144B)
#define FP_STRIDE 104        // p rows: 96 data + pad (208B)
#define FT_STRIDE 68         // S/T float rows (272B)
// byte offsets
#define FOFF_K 25600                     // q3s: 64*200*2
#define FOFF_V (FOFF_K + 2*32*FQ_STRIDE*2)   // 25600 + 25600 = 51200
#define FOFF_P (FOFF_V + 2*96*FV_STRIDE*2)   // 51200 + 27648 = 78848
#define FOFF_T (FOFF_P + 64*FP_STRIDE*2)     // 78848 + 13312 = 92160
#define FLASH_SMEM (FOFF_T + 64*FT_STRIDE*4) // 92160 + 17408 = 109568
#define KSTAGE (32*FQ_STRIDE)            // elems per K stage
#define VSTAGE (96*FV_STRIDE)            // elems per V stage

// ---------------- scratch ----------------
__device__ __align__(16) float g_qkv[(size_t)MROWS * QKVC];
__device__ __align__(16) __nv_bfloat16 g_q3[(size_t)BB * HH * NN * DH3];
__device__ __align__(16) __nv_bfloat16 g_k3[(size_t)BB * HH * NN * DH3];
__device__ __align__(16) __nv_bfloat16 g_v3[(size_t)BB * HH * 3 * NN * DH];
__device__ __align__(16) __nv_bfloat16 g_x3[(size_t)MROWS * K3];
__device__ __align__(16) __nv_bfloat16 g_wqkv3[(size_t)QKVC * K3];
__device__ __align__(16) __nv_bfloat16 g_att3[(size_t)MROWS * K3];
__device__ __align__(16) __nv_bfloat16 g_wout3[(size_t)DD * K3];

// ---------------- helpers ----------------
__device__ __forceinline__ uint32_t bfpack(__nv_bfloat16 a, __nv_bfloat16 b) {
    __nv_bfloat162 t;
    t.x = a; t.y = b;
    return *(uint32_t*)&t;
}

// Fast exp2 on FMA/ALU pipes (no MUFU). rel err ~2e-6.
__device__ __forceinline__ float exp2_fast(float t) {
    t = fmaxf(t, -126.0f);
    const float fi = t + 12582912.0f;
    const float r = t - (fi - 12582912.0f);
    float p = 1.3333558e-3f;
    p = fmaf(p, r, 9.6181291e-3f);
    p = fmaf(p, r, 5.5504109e-2f);
    p = fmaf(p, r, 2.4022651e-1f);
    p = fmaf(p, r, 6.9314718e-1f);
    p = fmaf(p, r, 1.0f);
    const int ib = __float_as_int(fi) - 0x4B400000;
    return __int_as_float(__float_as_int(p) + (ib << 23));
}

// ---------------- bf16 3-way split kernels ----------------
__global__ void __launch_bounds__(256)
split3_a(const float* __restrict__ X, __nv_bfloat16* __restrict__ Y, int n8)
{
    const int i = blockIdx.x * 256 + threadIdx.x;
    if (i >= n8) return;
    float f[8];
    *(float4*)&f[0] = *(const float4*)(X + (size_t)i * 8);
    *(float4*)&f[4] = *(const float4*)(X + (size_t)i * 8 + 4);
    __nv_bfloat16 o[24];
#pragma unroll
    for (int j = 0; j < 8; j++) {
        const __nv_bfloat16 hi = __float2bfloat16(f[j]);
        const __nv_bfloat16 lo = __float2bfloat16(f[j] - __bfloat162float(hi));
        o[3*j] = hi; o[3*j+1] = lo; o[3*j+2] = hi;
    }
    uint4* dst = (uint4*)(Y + (size_t)i * 24);
    const uint4* src = (const uint4*)o;
    dst[0] = src[0]; dst[1] = src[1]; dst[2] = src[2];
}

__global__ void __launch_bounds__(256)
split3_b(const float* __restrict__ X, __nv_bfloat16* __restrict__ Y, int n8)
{
    const int i = blockIdx.x * 256 + threadIdx.x;
    if (i >= n8) return;
    float f[8];
    *(float4*)&f[0] = *(const float4*)(X + (size_t)i * 8);
    *(float4*)&f[4] = *(const float4*)(X + (size_t)i * 8 + 4);
    __nv_bfloat16 o[24];
#pragma unroll
    for (int j = 0; j < 8; j++) {
        const __nv_bfloat16 hi = __float2bfloat16(f[j]);
        const __nv_bfloat16 lo = __float2bfloat16(f[j] - __bfloat162float(hi));
        o[3*j] = hi; o[3*j+1] = hi; o[3*j+2] = lo;
    }
    uint4* dst = (uint4*)(Y + (size_t)i * 24);
    const uint4* src = (const uint4*)o;
    dst[0] = src[0]; dst[1] = src[1]; dst[2] = src[2];
}

// ---------------- GEMM stage loader ----------------
__device__ __forceinline__ void gemm_load_stage(
    __nv_bfloat16* s, const __nv_bfloat16* A, const __nv_bfloat16* B,
    int m0, int n0, int k0, int K, int tid)
{
#pragma unroll
    for (int p = 0; p < 8; p++) {
        const int c = tid + p * 256;
        const int row = (c >> 3) & 127;
        const int col = (c & 7) * 8;
        if (p < 4) {
            __pipeline_memcpy_async(s + row * GSTRIDE + col,
                                    A + (size_t)(m0 + row) * K + k0 + col, 16);
        } else {
            __pipeline_memcpy_async(s + B_OFF + row * GSTRIDE + col,
                                    B + (size_t)(n0 + row) * K + k0 + col, 16);
        }
    }
    __pipeline_commit();
}

// ---------------- WMMA GEMM: C = A3 * B3^T ----------------
__global__ void __launch_bounds__(256, 2)
gemm_bf16_nt(const __nv_bfloat16* __restrict__ A, const __nv_bfloat16* __restrict__ B,
             float* __restrict__ C, int M, int N, int K)
{
    extern __shared__ __nv_bfloat16 smem[];

    const int tid = threadIdx.x;
    const int w = tid >> 5;
    const int wrow = w >> 2;
    const int wcol = w & 3;
    const int m0 = blockIdx.y * 128;
    const int n0 = blockIdx.x * 128;

    wmma::fragment<wmma::accumulator, 16, 16, 16, float> acc[4][2];
#pragma unroll
    for (int mi = 0; mi < 4; mi++)
#pragma unroll
        for (int ni = 0; ni < 2; ni++)
            wmma::fill_fragment(acc[mi][ni], 0.0f);

    const int ntiles = K / 64;

    gemm_load_stage(smem, A, B, m0, n0, 0, K, tid);

    for (int kt = 0; kt < ntiles; kt++) {
        const int s = kt & 1;
        if (kt + 1 < ntiles) {
            gemm_load_stage(smem + (s ^ 1) * STAGE_ELEMS, A, B, m0, n0,
                            (kt + 1) * 64, K, tid);
            __pipeline_wait_prior(1);
        } else {
            __pipeline_wait_prior(0);
        }
        __syncthreads();

        const __nv_bfloat16* as = smem + s * STAGE_ELEMS;
        const __nv_bfloat16* bs = as + B_OFF;
#pragma unroll
        for (int ks = 0; ks < 4; ks++) {
            wmma::fragment<wmma::matrix_b, 16, 16, 16, __nv_bfloat16, wmma::col_major> bf[2];
#pragma unroll
            for (int ni = 0; ni < 2; ni++)
                wmma::load_matrix_sync(bf[ni],
                    bs + (wcol * 32 + ni * 16) * GSTRIDE + ks * 16, GSTRIDE);
#pragma unroll
            for (int mi = 0; mi < 4; mi++) {
                wmma::fragment<wmma::matrix_a, 16, 16, 16, __nv_bfloat16, wmma::row_major> af;
                wmma::load_matrix_sync(af,
                    as + (wrow * 64 + mi * 16) * GSTRIDE + ks * 16, GSTRIDE);
#pragma unroll
                for (int ni = 0; ni < 2; ni++)
                    wmma::mma_sync(acc[mi][ni], af, bf[ni], acc[mi][ni]);
            }
        }
        __syncthreads();
    }

#pragma unroll
    for (int mi = 0; mi < 4; mi++)
#pragma unroll
        for (int ni = 0; ni < 2; ni++)
            wmma::store_matrix_sync(
                C + (size_t)(m0 + wrow * 64 + mi * 16) * N + n0 + wcol * 32 + ni * 16,
                acc[mi][ni], N, wmma::mem_row_major);
}

// ---------------- bias add ----------------
__global__ void __launch_bounds__(256)
bias_add(float* __restrict__ C, const float* __restrict__ bias, int n4, int N)
{
    const int i = blockIdx.x * 256 + threadIdx.x;
    if (i >= n4) return;
    const int col = (i * 4) & (N - 1);
    float4 v = *(float4*)(C + (size_t)i * 4);
    const float4 bv = *(const float4*)(bias + col);
    v.x += bv.x; v.y += bv.y; v.z += bv.z; v.w += bv.w;
    *(float4*)(C + (size_t)i * 4) = v;
}

// ---------------- RoPE + split: emits Q3/K3 [bh,N,192], V3 [bh,3N,64] -------
__global__ void __launch_bounds__(256)
rope3_kernel(const float* __restrict__ qkv, const float* __restrict__ rope,
             __nv_bfloat16* __restrict__ Q3, __nv_bfloat16* __restrict__ K3g,
             __nv_bfloat16* __restrict__ V3)
{
    const int idx = blockIdx.x * 256 + threadIdx.x;
    if (idx >= BB * NN * HH * 32) return;
    const int p2 = (idx & 31) << 1;
    const int h  = (idx >> 5) & (HH - 1);
    const int n  = (idx >> 9) & (NN - 1);
    const int b  = idx >> 20;

    const float f0 = rope[n * DH + p2];
    const float f1 = rope[n * DH + p2 + 1];
    float s0, c0, s1, c1;
    sincosf(f0, &s0, &c0);
    sincosf(f1, &s1, &c1);

    const size_t row = ((size_t)b * NN + n) * QKVC;
    const float2 q = *(const float2*)(qkv + row + h * DH + p2);
    const float2 k = *(const float2*)(qkv + row + OUTC + h * DH + p2);
    const float2 v = *(const float2*)(qkv + row + 2 * OUTC + h * DH + p2);

    const float SCALE = 0.125f;
    float qx = (q.x * c0 - q.y * s0) * SCALE;
    float qy = (q.y * c1 + q.x * s1) * SCALE;
    float kx = k.x * c0 - k.y * s0;
    float ky = k.y * c1 + k.x * s1;
    float vx = v.x * c0 - v.y * s0;
    float vy = v.y * c1 + v.x * s1;

    const __nv_bfloat16 qh0 = __float2bfloat16(qx);
    const __nv_bfloat16 ql0 = __float2bfloat16(qx - __bfloat162float(qh0));
    const __nv_bfloat16 qh1 = __float2bfloat16(qy);
    const __nv_bfloat16 ql1 = __float2bfloat16(qy - __bfloat162float(qh1));
    const __nv_bfloat16 kh0 = __float2bfloat16(kx);
    const __nv_bfloat16 kl0 = __float2bfloat16(kx - __bfloat162float(kh0));
    const __nv_bfloat16 kh1 = __float2bfloat16(ky);
    const __nv_bfloat16 kl1 = __float2bfloat16(ky - __bfloat162float(kh1));
    const __nv_bfloat16 vh0 = __float2bfloat16(vx);
    const __nv_bfloat16 vl0 = __float2bfloat16(vx - __bfloat162float(vh0));
    const __nv_bfloat16 vh1 = __float2bfloat16(vy);
    const __nv_bfloat16 vl1 = __float2bfloat16(vy - __bfloat162float(vh1));

    const int bh = b * HH + h;
    uint32_t* qp = (uint32_t*)(Q3 + ((size_t)bh * NN + n) * DH3 + 3 * p2);
    qp[0] = bfpack(qh0, ql0);
    qp[1] = bfpack(qh0, qh1);
    qp[2] = bfpack(ql1, qh1);
    uint32_t* kp = (uint32_t*)(K3g + ((size_t)bh * NN + n) * DH3 + 3 * p2);
    kp[0] = bfpack(kh0, kh0);
    kp[1] = bfpack(kl0, kh1);
    kp[2] = bfpack(kh1, kl1);
    uint32_t* vp = (uint32_t*)(V3 + ((size_t)bh * 3 * NN + 3 * n) * DH + p2);
    const uint32_t vhi = bfpack(vh0, vh1);
    vp[0] = vhi;
    vp[DH / 2] = vhi;
    vp[DH] = bfpack(vl0, vl1);
}

// ---------------- flash K/V tile prefetch (BN=32) ----------------
__device__ __forceinline__ void flash_prefetch32(
    __nv_bfloat16* ks, __nv_bfloat16* vsm,
    const __nv_bfloat16* Kbase, const __nv_bfloat16* Vbase,
    int kv0, int tid)
{
#pragma unroll
    for (int p = 0; p < 3; p++) {
        const int c = tid + p * 256;          // 0..767
        const int r = c / 24;                 // 0..31
        const int col = (c % 24) * 8;
        __pipeline_memcpy_async(ks + r * FQ_STRIDE + col,
                                Kbase + (size_t)(kv0 + r) * DH3 + col, 16);
    }
#pragma unroll
    for (int p = 0; p < 3; p++) {
        const int c = tid + p * 256;
        const int r = c >> 3;                 // 0..95
        const int col = (c & 7) * 8;
        __pipeline_memcpy_async(vsm + r * FV_STRIDE + col,
                                Vbase + (size_t)(3 * kv0 + r) * DH + col, 16);
    }
    __pipeline_commit();
}

// ---------------- Flash attention: BM=64, BN=32, 2 blocks/SM ---------------
// 8 warps; S-phase warp tile 16x16 (4m x 2n); PV-phase 16x32 (4m x 2n).
// O/m/l live in registers. Epilogue writes att3 (pattern-a split) directly.
__global__ void __launch_bounds__(256, 2)
flash_wmma(const __nv_bfloat16* __restrict__ Q3,
           const __nv_bfloat16* __restrict__ Kg3,
           const __nv_bfloat16* __restrict__ Vg3,
           __nv_bfloat16* __restrict__ ATT3)
{
    extern __shared__ char fsm[];
    __nv_bfloat16* q3s = (__nv_bfloat16*)fsm;
    __nv_bfloat16* k3s = (__nv_bfloat16*)(fsm + FOFF_K);
    __nv_bfloat16* v3s = (__nv_bfloat16*)(fsm + FOFF_V);
    __nv_bfloat16* p3s = (__nv_bfloat16*)(fsm + FOFF_P);
    float* Tsm = (float*)(fsm + FOFF_T);      // S (64x32) then T=PV (64x64)

    const int tid = threadIdx.x;
    const int w = tid >> 5;
    const int wm = (w >> 1) * 16;
    const int wn = (w & 1) * 16;        // S-phase n offset
    const int wt = (w & 1) * 32;        // PV-phase n offset
    const int qt = blockIdx.x;
    const int bh = blockIdx.y;
    const int q0 = qt * 64;

    const __nv_bfloat16* Qbase = Q3 + ((size_t)bh * NN + q0) * DH3;
    const __nv_bfloat16* Kbase = Kg3 + (size_t)bh * NN * DH3;
    const __nv_bfloat16* Vbase = Vg3 + (size_t)bh * 3 * NN * DH;

    flash_prefetch32(k3s, v3s, Kbase, Vbase, 0, tid);

    // Q3 tile: 64 rows x 192 elems
#pragma unroll
    for (int p = 0; p < 6; p++) {
        const int c = tid + p * 256;
        const int r = c / 24;
        const int col = (c % 24) * 8;
        *(uint4*)(q3s + r * FQ_STRIDE + col) =
            *(const uint4*)(Qbase + (size_t)r * DH3 + col);
    }

    const int sr = tid >> 2;            // row 0..63
    const int sq = tid & 3;
    const int sj0 = sq * 8;             // softmax col base (32 cols)
    const int od0 = sq * 16;            // O col base (64 dims)

    float m_i = -1e30f, l_i = 0.f;
    float o[16];
#pragma unroll
    for (int j = 0; j < 16; j++) o[j] = 0.f;

    const int last = 2 * qt + 1;
    for (int kt = 0; kt <= last; kt++) {
        const int s = kt & 1;
        const int kv0 = kt * FBN;
        if (kt < last) {
            flash_prefetch32(k3s + (s ^ 1) * KSTAGE, v3s + (s ^ 1) * VSTAGE,
                             Kbase, Vbase, kv0 + FBN, tid);
            __pipeline_wait_prior(1);
        } else {
            __pipeline_wait_prior(0);
        }
        __syncthreads();

        const __nv_bfloat16* ks = k3s + s * KSTAGE;
        const __nv_bfloat16* vs = v3s + s * VSTAGE;

        // S = Q3 * K3^T (64x32)
        {
            wmma::fragment<wmma::accumulator, 16, 16, 16, float> sa;
            wmma::fill_fragment(sa, 0.f);
#pragma unroll
            for (int k = 0; k < 12; k++) {
                wmma::fragment<wmma::matrix_a, 16, 16, 16, __nv_bfloat16, wmma::row_major> af;
                wmma::load_matrix_sync(af, q3s + wm * FQ_STRIDE + k * 16, FQ_STRIDE);
                wmma::fragment<wmma::matrix_b, 16, 16, 16, __nv_bfloat16, wmma::col_major> bf;
                wmma::load_matrix_sync(bf, ks + wn * FQ_STRIDE + k * 16, FQ_STRIDE);
                wmma::mma_sync(sa, af, bf, sa);
            }
            wmma::store_matrix_sync(Tsm + wm * FT_STRIDE + wn, sa, FT_STRIDE,
                                    wmma::mem_row_major);
        }
        __syncthreads();

        // online softmax (each of 4 row-threads keeps redundant m/l)
        float alpha;
        {
            float sv[8];
#pragma unroll
            for (int j = 0; j < 8; j += 4)
                *(float4*)&sv[j] = *(float4*)&Tsm[sr * FT_STRIDE + sj0 + j];
            if (kv0 + FBN - 1 > q0) {
#pragma unroll
                for (int j = 0; j < 8; j++)
                    if (kv0 + sj0 + j > q0 + sr) sv[j] = -1e30f;
            }
            float rm = sv[0];
#pragma unroll
            for (int j = 1; j < 8; j++) rm = fmaxf(rm, sv[j]);
            rm = fmaxf(rm, __shfl_xor_sync(0xffffffffu, rm, 1));
            rm = fmaxf(rm, __shfl_xor_sync(0xffffffffu, rm, 2));
            const float mnew = fmaxf(m_i, rm);
            float rs = 0.f;
            uint32_t* prow = (uint32_t*)(p3s + sr * FP_STRIDE + 3 * sj0);
#pragma unroll
            for (int j = 0; j < 8; j += 2) {
                const float p0 = exp2_fast((sv[j] - mnew) * 1.4426950f);
                const float p1 = exp2_fast((sv[j + 1] - mnew) * 1.4426950f);
                rs += p0 + p1;
                const __nv_bfloat16 h0 = __float2bfloat16(p0);
                const __nv_bfloat16 l0 = __float2bfloat16(p0 - __bfloat162float(h0));
                const __nv_bfloat16 h1 = __float2bfloat16(p1);
                const __nv_bfloat16 l1 = __float2bfloat16(p1 - __bfloat162float(h1));
                prow[3 * (j >> 1) + 0] = bfpack(h0, l0);
                prow[3 * (j >> 1) + 1] = bfpack(h0, h1);
                prow[3 * (j >> 1) + 2] = bfpack(l1, h1);
            }
            rs += __shfl_xor_sync(0xffffffffu, rs, 1);
            rs += __shfl_xor_sync(0xffffffffu, rs, 2);
            alpha = exp2_fast((m_i - mnew) * 1.4426950f);
            l_i = l_i * alpha + rs;
            m_i = mnew;
        }
        __syncthreads();

        // T = P3 * V3 (64x64, K=96)
        {
            wmma::fragment<wmma::accumulator, 16, 16, 16, float> ta0, ta1;
            wmma::fill_fragment(ta0, 0.f);
            wmma::fill_fragment(ta1, 0.f);
#pragma unroll
            for (int k = 0; k < 6; k++) {
                wmma::fragment<wmma::matrix_a, 16, 16, 16, __nv_bfloat16, wmma::row_major> af;
                wmma::load_matrix_sync(af, p3s + wm * FP_STRIDE + k * 16, FP_STRIDE);
                wmma::fragment<wmma::matrix_b, 16, 16, 16, __nv_bfloat16, wmma::row_major> bf;
                wmma::load_matrix_sync(bf, vs + k * 16 * FV_STRIDE + wt, FV_STRIDE);
                wmma::mma_sync(ta0, af, bf, ta0);
                wmma::load_matrix_sync(bf, vs + k * 16 * FV_STRIDE + wt + 16, FV_STRIDE);
                wmma::mma_sync(ta1, af, bf, ta1);
            }
            wmma::store_matrix_sync(Tsm + wm * FT_STRIDE + wt, ta0, FT_STRIDE,
                                    wmma::mem_row_major);
            wmma::store_matrix_sync(Tsm + wm * FT_STRIDE + wt + 16, ta1, FT_STRIDE,
                                    wmma::mem_row_major);
        }
        __syncthreads();

        // O = O*alpha + T (registers; next top-of-loop sync protects Tsm)
#pragma unroll
        for (int j = 0; j < 16; j += 4) {
            const float4 t = *(float4*)&Tsm[sr * FT_STRIDE + od0 + j];
            o[j + 0] = fmaf(o[j + 0], alpha, t.x);
            o[j + 1] = fmaf(o[j + 1], alpha, t.y);
            o[j + 2] = fmaf(o[j + 2], alpha, t.z);
            o[j + 3] = fmaf(o[j + 3], alpha, t.w);
        }
    }

    // epilogue: write att3 directly (pattern a: hi,lo,hi), row-major [4096,3072]
    {
        const int b = bh >> 4;
        const int h = bh & 15;
        const float inv = 1.f / l_i;
        uint32_t* op = (uint32_t*)(ATT3 + (size_t)(b * NN + q0 + sr) * K3 +
                                   3 * (h * DH + od0));
#pragma unroll
        for (int j = 0; j < 16; j += 2) {
            const float e0 = o[j] * inv;
            const float e1 = o[j + 1] * inv;
            const __nv_bfloat16 h0 = __float2bfloat16(e0);
            const __nv_bfloat16 l0 = __float2bfloat16(e0 - __bfloat162float(h0));
            const __nv_bfloat16 h1 = __float2bfloat16(e1);
            const __nv_bfloat16 l1 = __float2bfloat16(e1 - __bfloat162float(h1));
            op[3 * (j >> 1) + 0] = bfpack(h0, l0);
            op[3 * (j >> 1) + 1] = bfpack(h0, h1);
            op[3 * (j >> 1) + 2] = bfpack(l1, h1);
        }
    }
}

// ---------------- launch ----------------
extern "C" void kernel_launch(void* const* d_in, const int* in_sizes, int n_in,
                              void* d_out, int out_size)
{
    const float* x            = (const float*)d_in[0];
    const float* rope         = (const float*)d_in[2];
    const float* Wqkv         = (const float*)d_in[3];
    const float* Wout         = (const float*)d_in[4];
    const float* bout         = (const float*)d_in[5];
    float* out = (float*)d_out;

    float *qkv;
    __nv_bfloat16 *q3, *k3, *v3, *x3, *wqkv3, *att3, *wout3;
    cudaGetSymbolAddress((void**)&qkv, g_qkv);
    cudaGetSymbolAddress((void**)&q3,  g_q3);
    cudaGetSymbolAddress((void**)&k3,  g_k3);
    cudaGetSymbolAddress((void**)&v3,  g_v3);
    cudaGetSymbolAddress((void**)&x3,    g_x3);
    cudaGetSymbolAddress((void**)&wqkv3, g_wqkv3);
    cudaGetSymbolAddress((void**)&att3,  g_att3);
    cudaGetSymbolAddress((void**)&wout3, g_wout3);

    cudaFuncSetAttribute(gemm_bf16_nt, cudaFuncAttributeMaxDynamicSharedMemorySize,
                         GEMM_SMEM);
    cudaFuncSetAttribute(flash_wmma, cudaFuncAttributeMaxDynamicSharedMemorySize,
                         FLASH_SMEM);

    // splits (x and both weight matrices)
    split3_a<<<(MROWS * DD / 8 + 255) / 256, 256>>>(x, x3, MROWS * DD / 8);
    split3_b<<<(QKVC * DD / 8 + 255) / 256, 256>>>(Wqkv, wqkv3, QKVC * DD / 8);
    split3_b<<<(DD * DD / 8 + 255) / 256, 256>>>(Wout, wout3, DD * DD / 8);

    // 1) qkv = x @ Wqkv^T
    gemm_bf16_nt<<<dim3(QKVC / 128, MROWS / 128), 256, GEMM_SMEM>>>(
        x3, wqkv3, qkv, MROWS, QKVC, K3);

    // 2) RoPE + split -> Q3, K3, V3
    rope3_kernel<<<(BB * NN * HH * 32 + 255) / 256, 256>>>(qkv, rope, q3, k3, v3);

    // 3) causal flash attention -> att3 (pre-split for out-proj)
    flash_wmma<<<dim3(NN / 64, BB * HH), 256, FLASH_SMEM>>>(q3, k3, v3, att3);

    // 4) out = att @ Wout^T + bias
    gemm_bf16_nt<<<dim3(OUTC / 128, MROWS / 128), 256, GEMM_SMEM>>>(
        att3, wout3, out, MROWS, OUTC, K3);
    bias_add<<<(MROWS * OUTC / 4 + 255) / 256, 256>>>(
        out, bout, MROWS * OUTC / 4, OUTC);
}

// round 10
// speedup vs baseline: 1.3429x; 1.3429x over previous
#include <cuda_runtime.h>
#include <cuda_bf16.h>
#include <mma.h>
#include <cuda_pipeline.h>
#include <float.h>
#include <math.h>
#include <stdint.h>

using namespace nvcuda;

// Problem constants
#define BB 2
#define NN 2048
#define DD 1024
#define HH 16
#define DH 64
#define DH3 (3*DH)           // 192
#define MROWS (BB*NN)        // 4096
#define QKVC (3*HH*DH)       // 3072
#define OUTC (HH*DH)         // 1024
#define K3 (3*DD)            // 3072

// GEMM tile config
#define GSTRIDE 72
#define STAGE_ELEMS (2 * 128 * GSTRIDE)
#define B_OFF (128 * GSTRIDE)
#define GEMM_SMEM (2 * STAGE_ELEMS * 2)

// Flash config: BM=128 q rows, BN=64 kv cols, 8 warps, register accumulators.
#define SQ 200               // q/k/p smem row stride (elems): 400B, odd*16B
#define SV 72                // v smem row stride: 144B, odd*16B
#define FOFF_K 51200         // q3s: 128*200*2
#define FOFF_V 102400        // k3s: 2*64*200*2
#define FOFF_P 157696        // v3s: 2*192*72*2
#define FLASH_SMEM 208896    // + p3s: 128*200*2
#define KSTAGE (64 * SQ)     // elems
#define VSTAGE (192 * SV)

// ---------------- scratch ----------------
__device__ __align__(16) float g_qkv[(size_t)MROWS * QKVC];
__device__ __align__(16) __nv_bfloat16 g_q3[(size_t)BB * HH * NN * DH3];
__device__ __align__(16) __nv_bfloat16 g_k3[(size_t)BB * HH * NN * DH3];
__device__ __align__(16) __nv_bfloat16 g_v3[(size_t)BB * HH * 3 * NN * DH];
__device__ __align__(16) __nv_bfloat16 g_x3[(size_t)MROWS * K3];
__device__ __align__(16) __nv_bfloat16 g_wqkv3[(size_t)QKVC * K3];
__device__ __align__(16) __nv_bfloat16 g_att3[(size_t)MROWS * K3];
__device__ __align__(16) __nv_bfloat16 g_wout3[(size_t)DD * K3];

// ---------------- helpers ----------------
__device__ __forceinline__ uint32_t bfpack(__nv_bfloat16 a, __nv_bfloat16 b) {
    __nv_bfloat162 t;
    t.x = a; t.y = b;
    return *(uint32_t*)&t;
}

// Fast exp2 on FMA/ALU pipes (no MUFU). rel err ~2e-6.
__device__ __forceinline__ float exp2_fast(float t) {
    t = fmaxf(t, -126.0f);
    const float fi = t + 12582912.0f;
    const float r = t - (fi - 12582912.0f);
    float p = 1.3333558e-3f;
    p = fmaf(p, r, 9.6181291e-3f);
    p = fmaf(p, r, 5.5504109e-2f);
    p = fmaf(p, r, 2.4022651e-1f);
    p = fmaf(p, r, 6.9314718e-1f);
    p = fmaf(p, r, 1.0f);
    const int ib = __float_as_int(fi) - 0x4B400000;
    return __int_as_float(__float_as_int(p) + (ib << 23));
}

// Raw MMA / ldmatrix wrappers. Brace characters in the PTX strings are written
// as octal escapes so the source contains no literal braces inside strings.
__device__ __forceinline__ void mma16816(float* d, const uint32_t* a, const uint32_t* b) {
    asm volatile(
        "mma.sync.aligned.m16n8k16.row.col.f32.bf16.bf16.f32 "
        "\173%0,%1,%2,%3\175,\173%4,%5,%6,%7\175,\173%8,%9\175,\173%0,%1,%2,%3\175;"
        : "+f"(d[0]), "+f"(d[1]), "+f"(d[2]), "+f"(d[3])
        : "r"(a[0]), "r"(a[1]), "r"(a[2]), "r"(a[3]), "r"(b[0]), "r"(b[1]));
}
__device__ __forceinline__ void ldsm4(uint32_t* r, uint32_t addr) {
    asm volatile(
        "ldmatrix.sync.aligned.m8n8.x4.shared.b16 \173%0,%1,%2,%3\175,[%4];"
        : "=r"(r[0]), "=r"(r[1]), "=r"(r[2]), "=r"(r[3]) : "r"(addr));
}
__device__ __forceinline__ void ldsm4t(uint32_t* r, uint32_t addr) {
    asm volatile(
        "ldmatrix.sync.aligned.m8n8.x4.trans.shared.b16 \173%0,%1,%2,%3\175,[%4];"
        : "=r"(r[0]), "=r"(r[1]), "=r"(r[2]), "=r"(r[3]) : "r"(addr));
}

// ---------------- bf16 3-way split kernels ----------------
__global__ void __launch_bounds__(256)
split3_a(const float* __restrict__ X, __nv_bfloat16* __restrict__ Y, int n8)
{
    const int i = blockIdx.x * 256 + threadIdx.x;
    if (i >= n8) return;
    float f[8];
    *(float4*)&f[0] = *(const float4*)(X + (size_t)i * 8);
    *(float4*)&f[4] = *(const float4*)(X + (size_t)i * 8 + 4);
    __nv_bfloat16 o[24];
#pragma unroll
    for (int j = 0; j < 8; j++) {
        const __nv_bfloat16 hi = __float2bfloat16(f[j]);
        const __nv_bfloat16 lo = __float2bfloat16(f[j] - __bfloat162float(hi));
        o[3*j] = hi; o[3*j+1] = lo; o[3*j+2] = hi;
    }
    uint4* dst = (uint4*)(Y + (size_t)i * 24);
    const uint4* src = (const uint4*)o;
    dst[0] = src[0]; dst[1] = src[1]; dst[2] = src[2];
}

__global__ void __launch_bounds__(256)
split3_b(const float* __restrict__ X, __nv_bfloat16* __restrict__ Y, int n8)
{
    const int i = blockIdx.x * 256 + threadIdx.x;
    if (i >= n8) return;
    float f[8];
    *(float4*)&f[0] = *(const float4*)(X + (size_t)i * 8);
    *(float4*)&f[4] = *(const float4*)(X + (size_t)i * 8 + 4);
    __nv_bfloat16 o[24];
#pragma unroll
    for (int j = 0; j < 8; j++) {
        const __nv_bfloat16 hi = __float2bfloat16(f[j]);
        const __nv_bfloat16 lo = __float2bfloat16(f[j] - __bfloat162float(hi));
        o[3*j] = hi; o[3*j+1] = hi; o[3*j+2] = lo;
    }
    uint4* dst = (uint4*)(Y + (size_t)i * 24);
    const uint4* src = (const uint4*)o;
    dst[0] = src[0]; dst[1] = src[1]; dst[2] = src[2];
}

// ---------------- GEMM stage loader ----------------
__device__ __forceinline__ void gemm_load_stage(
    __nv_bfloat16* s, const __nv_bfloat16* A, const __nv_bfloat16* B,
    int m0, int n0, int k0, int K, int tid)
{
#pragma unroll
    for (int p = 0; p < 8; p++) {
        const int c = tid + p * 256;
        const int row = (c >> 3) & 127;
        const int col = (c & 7) * 8;
        if (p < 4) {
            __pipeline_memcpy_async(s + row * GSTRIDE + col,
                                    A + (size_t)(m0 + row) * K + k0 + col, 16);
        } else {
            __pipeline_memcpy_async(s + B_OFF + row * GSTRIDE + col,
                                    B + (size_t)(n0 + row) * K + k0 + col, 16);
        }
    }
    __pipeline_commit();
}

// ---------------- WMMA GEMM: C = A3 * B3^T ----------------
__global__ void __launch_bounds__(256, 2)
gemm_bf16_nt(const __nv_bfloat16* __restrict__ A, const __nv_bfloat16* __restrict__ B,
             float* __restrict__ C, int M, int N, int K)
{
    extern __shared__ __nv_bfloat16 smem[];

    const int tid = threadIdx.x;
    const int w = tid >> 5;
    const int wrow = w >> 2;
    const int wcol = w & 3;
    const int m0 = blockIdx.y * 128;
    const int n0 = blockIdx.x * 128;

    wmma::fragment<wmma::accumulator, 16, 16, 16, float> acc[4][2];
#pragma unroll
    for (int mi = 0; mi < 4; mi++)
#pragma unroll
        for (int ni = 0; ni < 2; ni++)
            wmma::fill_fragment(acc[mi][ni], 0.0f);

    const int ntiles = K / 64;

    gemm_load_stage(smem, A, B, m0, n0, 0, K, tid);

    for (int kt = 0; kt < ntiles; kt++) {
        const int s = kt & 1;
        if (kt + 1 < ntiles) {
            gemm_load_stage(smem + (s ^ 1) * STAGE_ELEMS, A, B, m0, n0,
                            (kt + 1) * 64, K, tid);
            __pipeline_wait_prior(1);
        } else {
            __pipeline_wait_prior(0);
        }
        __syncthreads();

        const __nv_bfloat16* as = smem + s * STAGE_ELEMS;
        const __nv_bfloat16* bs = as + B_OFF;
#pragma unroll
        for (int ks = 0; ks < 4; ks++) {
            wmma::fragment<wmma::matrix_b, 16, 16, 16, __nv_bfloat16, wmma::col_major> bf[2];
#pragma unroll
            for (int ni = 0; ni < 2; ni++)
                wmma::load_matrix_sync(bf[ni],
                    bs + (wcol * 32 + ni * 16) * GSTRIDE + ks * 16, GSTRIDE);
#pragma unroll
            for (int mi = 0; mi < 4; mi++) {
                wmma::fragment<wmma::matrix_a, 16, 16, 16, __nv_bfloat16, wmma::row_major> af;
                wmma::load_matrix_sync(af,
                    as + (wrow * 64 + mi * 16) * GSTRIDE + ks * 16, GSTRIDE);
#pragma unroll
                for (int ni = 0; ni < 2; ni++)
                    wmma::mma_sync(acc[mi][ni], af, bf[ni], acc[mi][ni]);
            }
        }
        __syncthreads();
    }

#pragma unroll
    for (int mi = 0; mi < 4; mi++)
#pragma unroll
        for (int ni = 0; ni < 2; ni++)
            wmma::store_matrix_sync(
                C + (size_t)(m0 + wrow * 64 + mi * 16) * N + n0 + wcol * 32 + ni * 16,
                acc[mi][ni], N, wmma::mem_row_major);
}

// ---------------- bias add ----------------
__global__ void __launch_bounds__(256)
bias_add(float* __restrict__ C, const float* __restrict__ bias, int n4, int N)
{
    const int i = blockIdx.x * 256 + threadIdx.x;
    if (i >= n4) return;
    const int col = (i * 4) & (N - 1);
    float4 v = *(float4*)(C + (size_t)i * 4);
    const float4 bv = *(const float4*)(bias + col);
    v.x += bv.x; v.y += bv.y; v.z += bv.z; v.w += bv.w;
    *(float4*)(C + (size_t)i * 4) = v;
}

// ---------------- RoPE + split: Q3/K3 [bh,N,192], V3 [bh,3N,64] ------------
__global__ void __launch_bounds__(256)
rope3_kernel(const float* __restrict__ qkv, const float* __restrict__ rope,
             __nv_bfloat16* __restrict__ Q3, __nv_bfloat16* __restrict__ K3g,
             __nv_bfloat16* __restrict__ V3)
{
    const int idx = blockIdx.x * 256 + threadIdx.x;
    if (idx >= BB * NN * HH * 32) return;
    const int p2 = (idx & 31) << 1;
    const int h  = (idx >> 5) & (HH - 1);
    const int n  = (idx >> 9) & (NN - 1);
    const int b  = idx >> 20;

    const float f0 = rope[n * DH + p2];
    const float f1 = rope[n * DH + p2 + 1];
    float s0, c0, s1, c1;
    sincosf(f0, &s0, &c0);
    sincosf(f1, &s1, &c1);

    const size_t row = ((size_t)b * NN + n) * QKVC;
    const float2 q = *(const float2*)(qkv + row + h * DH + p2);
    const float2 k = *(const float2*)(qkv + row + OUTC + h * DH + p2);
    const float2 v = *(const float2*)(qkv + row + 2 * OUTC + h * DH + p2);

    const float SCALE = 0.125f;
    float qx = (q.x * c0 - q.y * s0) * SCALE;
    float qy = (q.y * c1 + q.x * s1) * SCALE;
    float kx = k.x * c0 - k.y * s0;
    float ky = k.y * c1 + k.x * s1;
    float vx = v.x * c0 - v.y * s0;
    float vy = v.y * c1 + v.x * s1;

    const __nv_bfloat16 qh0 = __float2bfloat16(qx);
    const __nv_bfloat16 ql0 = __float2bfloat16(qx - __bfloat162float(qh0));
    const __nv_bfloat16 qh1 = __float2bfloat16(qy);
    const __nv_bfloat16 ql1 = __float2bfloat16(qy - __bfloat162float(qh1));
    const __nv_bfloat16 kh0 = __float2bfloat16(kx);
    const __nv_bfloat16 kl0 = __float2bfloat16(kx - __bfloat162float(kh0));
    const __nv_bfloat16 kh1 = __float2bfloat16(ky);
    const __nv_bfloat16 kl1 = __float2bfloat16(ky - __bfloat162float(kh1));
    const __nv_bfloat16 vh0 = __float2bfloat16(vx);
    const __nv_bfloat16 vl0 = __float2bfloat16(vx - __bfloat162float(vh0));
    const __nv_bfloat16 vh1 = __float2bfloat16(vy);
    const __nv_bfloat16 vl1 = __float2bfloat16(vy - __bfloat162float(vh1));

    const int bh = b * HH + h;
    uint32_t* qp = (uint32_t*)(Q3 + ((size_t)bh * NN + n) * DH3 + 3 * p2);
    qp[0] = bfpack(qh0, ql0);
    qp[1] = bfpack(qh0, qh1);
    qp[2] = bfpack(ql1, qh1);
    uint32_t* kp = (uint32_t*)(K3g + ((size_t)bh * NN + n) * DH3 + 3 * p2);
    kp[0] = bfpack(kh0, kh0);
    kp[1] = bfpack(kl0, kh1);
    kp[2] = bfpack(kh1, kl1);
    uint32_t* vp = (uint32_t*)(V3 + ((size_t)bh * 3 * NN + 3 * n) * DH + p2);
    const uint32_t vhi = bfpack(vh0, vh1);
    vp[0] = vhi;
    vp[DH / 2] = vhi;
    vp[DH] = bfpack(vl0, vl1);
}

// ---------------- flash K/V stage prefetch (BN=64) ----------------
__device__ __forceinline__ void flash_prefetch(
    __nv_bfloat16* ks, __nv_bfloat16* vsm,
    const __nv_bfloat16* Kbase, const __nv_bfloat16* Vbase,
    int kv0, int tid)
{
#pragma unroll
    for (int p = 0; p < 6; p++) {
        const int c = tid + p * 256;          // 0..1535
        const int r = c / 24;                 // 0..63
        const int col = (c % 24) * 8;
        __pipeline_memcpy_async(ks + r * SQ + col,
                                Kbase + (size_t)(kv0 + r) * DH3 + col, 16);
    }
#pragma unroll
    for (int p = 0; p < 6; p++) {
        const int c = tid + p * 256;
        const int r = c >> 3;                 // 0..191
        const int col = (c & 7) * 8;
        __pipeline_memcpy_async(vsm + r * SV + col,
                                Vbase + (size_t)(3 * kv0 + r) * DH + col, 16);
    }
    __pipeline_commit();
}

// ---------------- Flash attention: register mma, BM=128, BN=64 -------------
// 8 warps, warp w owns q rows [16w,16w+16). S and O accumulate in registers
// (m16n8k16 layout: rows lane>>2 & +8, cols 2*(lane&3)+{0,1} per n8-frag).
// Softmax in registers via quad shfl. P makes one smem trip (tripled split).
__global__ void __launch_bounds__(256)
flash_mma(const __nv_bfloat16* __restrict__ Q3,
          const __nv_bfloat16* __restrict__ Kg3,
          const __nv_bfloat16* __restrict__ Vg3,
          __nv_bfloat16* __restrict__ ATT3)
{
    extern __shared__ char fsm[];
    __nv_bfloat16* q3s = (__nv_bfloat16*)fsm;
    __nv_bfloat16* k3s = (__nv_bfloat16*)(fsm + FOFF_K);
    __nv_bfloat16* v3s = (__nv_bfloat16*)(fsm + FOFF_V);
    __nv_bfloat16* p3s = (__nv_bfloat16*)(fsm + FOFF_P);

    const int tid = threadIdx.x;
    const int w = tid >> 5;
    const int lane = tid & 31;
    const int qt = blockIdx.x;
    const int bh = blockIdx.y;
    const int q0 = qt * 128;

    const __nv_bfloat16* Qbase = Q3 + ((size_t)bh * NN + q0) * DH3;
    const __nv_bfloat16* Kbase = Kg3 + (size_t)bh * NN * DH3;
    const __nv_bfloat16* Vbase = Vg3 + (size_t)bh * 3 * NN * DH;

    const uint32_t qsb = (uint32_t)__cvta_generic_to_shared(q3s);
    const uint32_t ksb = (uint32_t)__cvta_generic_to_shared(k3s);
    const uint32_t vsb = (uint32_t)__cvta_generic_to_shared(v3s);
    const uint32_t psb = (uint32_t)__cvta_generic_to_shared(p3s);

    flash_prefetch(k3s, v3s, Kbase, Vbase, 0, tid);

    // Q3 tile: 128 rows x 192 elems
#pragma unroll
    for (int p = 0; p < 12; p++) {
        const int c = tid + p * 256;
        const int r = c / 24;
        const int col = (c % 24) * 8;
        *(uint4*)(q3s + r * SQ + col) =
            *(const uint4*)(Qbase + (size_t)r * DH3 + col);
    }

    const int r0 = lane >> 2;           // 0..7
    const int cq = lane & 3;
    const int mrow = 16 * w;            // warp's first q row (block-local)
    const int grow0 = q0 + mrow + r0;   // global q rows for this thread
    const int grow1 = grow0 + 8;

    // ldmatrix lane address components (elems)
    const int a_row = mrow + (lane & 15);
    const int a_col8 = (lane >> 4) * 8;
    const int b_rowk = ((lane >> 4) << 3) + (lane & 7);   // K tile n-row within 16
    const int b_colk8 = ((lane >> 3) & 1) * 8;
    const int v_rowk = lane & 15;
    const int v_col8 = (lane >> 4) * 8;

    float o[8][4];
#pragma unroll
    for (int d = 0; d < 8; d++)
#pragma unroll
        for (int e = 0; e < 4; e++) o[d][e] = 0.f;
    float m0 = -1e30f, m1 = -1e30f, l0 = 0.f, l1 = 0.f;

    const int last = 2 * qt + 1;
    for (int kt = 0; kt <= last; kt++) {
        const int st = kt & 1;
        const int kv0 = kt * 64;

        __pipeline_wait_prior(0);
        __syncthreads();
        if (kt < last)
            flash_prefetch(k3s + (st ^ 1) * KSTAGE, v3s + (st ^ 1) * VSTAGE,
                           Kbase, Vbase, kv0 + 64, tid);

        const bool active = (kv0 <= q0 + mrow + 15);
        const uint32_t kst = ksb + (uint32_t)(st * KSTAGE * 2);
        const uint32_t vst = vsb + (uint32_t)(st * VSTAGE * 2);

        if (active) {
            // ---- S = Q3 * K3^T (16 x 64), registers ----
            float sacc[8][4];
#pragma unroll
            for (int d = 0; d < 8; d++)
#pragma unroll
                for (int e = 0; e < 4; e++) sacc[d][e] = 0.f;

#pragma unroll
            for (int kk = 0; kk < 12; kk++) {
                uint32_t a[4];
                ldsm4(a, qsb + (uint32_t)((a_row * SQ + kk * 16 + a_col8) * 2));
#pragma unroll
                for (int np = 0; np < 4; np++) {
                    uint32_t b[4];
                    ldsm4(b, kst + (uint32_t)(((np * 16 + b_rowk) * SQ +
                                               kk * 16 + b_colk8) * 2));
                    mma16816(sacc[2 * np], a, b);
                    mma16816(sacc[2 * np + 1], a, b + 2);
                }
            }

            // ---- masking + online softmax in registers ----
            if (kv0 + 63 > grow0) {
#pragma unroll
                for (int d = 0; d < 8; d++) {
                    const int col = kv0 + d * 8 + 2 * cq;
                    if (col > grow0)     sacc[d][0] = -1e30f;
                    if (col + 1 > grow0) sacc[d][1] = -1e30f;
                    if (col > grow1)     sacc[d][2] = -1e30f;
                    if (col + 1 > grow1) sacc[d][3] = -1e30f;
                }
            }
            float rm0 = sacc[0][0], rm1 = sacc[0][2];
#pragma unroll
            for (int d = 0; d < 8; d++) {
                rm0 = fmaxf(rm0, fmaxf(sacc[d][0], sacc[d][1]));
                rm1 = fmaxf(rm1, fmaxf(sacc[d][2], sacc[d][3]));
            }
            rm0 = fmaxf(rm0, __shfl_xor_sync(0xffffffffu, rm0, 1));
            rm0 = fmaxf(rm0, __shfl_xor_sync(0xffffffffu, rm0, 2));
            rm1 = fmaxf(rm1, __shfl_xor_sync(0xffffffffu, rm1, 1));
            rm1 = fmaxf(rm1, __shfl_xor_sync(0xffffffffu, rm1, 2));
            const float mn0 = fmaxf(m0, rm0);
            const float mn1 = fmaxf(m1, rm1);
            const float al0 = exp2_fast((m0 - mn0) * 1.4426950f);
            const float al1 = exp2_fast((m1 - mn1) * 1.4426950f);
            m0 = mn0; m1 = mn1;

            float rs0 = 0.f, rs1 = 0.f;
            char* prow0 = (char*)p3s + (mrow + r0) * (SQ * 2) + 12 * cq;
            char* prow1 = prow0 + 8 * (SQ * 2);
#pragma unroll
            for (int d = 0; d < 8; d++) {
                const float p00 = exp2_fast((sacc[d][0] - mn0) * 1.4426950f);
                const float p01 = exp2_fast((sacc[d][1] - mn0) * 1.4426950f);
                const float p10 = exp2_fast((sacc[d][2] - mn1) * 1.4426950f);
                const float p11 = exp2_fast((sacc[d][3] - mn1) * 1.4426950f);
                rs0 += p00 + p01;
                rs1 += p10 + p11;
                const __nv_bfloat16 h00 = __float2bfloat16(p00);
                const __nv_bfloat16 g00 = __float2bfloat16(p00 - __bfloat162float(h00));
                const __nv_bfloat16 h01 = __float2bfloat16(p01);
                const __nv_bfloat16 g01 = __float2bfloat16(p01 - __bfloat162float(h01));
                const __nv_bfloat16 h10 = __float2bfloat16(p10);
                const __nv_bfloat16 g10 = __float2bfloat16(p10 - __bfloat162float(h10));
                const __nv_bfloat16 h11 = __float2bfloat16(p11);
                const __nv_bfloat16 g11 = __float2bfloat16(p11 - __bfloat162float(h11));
                uint32_t* w0 = (uint32_t*)(prow0 + 48 * d);
                w0[0] = bfpack(h00, g00);
                w0[1] = bfpack(h00, h01);
                w0[2] = bfpack(g01, h01);
                uint32_t* w1 = (uint32_t*)(prow1 + 48 * d);
                w1[0] = bfpack(h10, g10);
                w1[1] = bfpack(h10, h11);
                w1[2] = bfpack(g11, h11);
            }
            rs0 += __shfl_xor_sync(0xffffffffu, rs0, 1);
            rs0 += __shfl_xor_sync(0xffffffffu, rs0, 2);
            rs1 += __shfl_xor_sync(0xffffffffu, rs1, 1);
            rs1 += __shfl_xor_sync(0xffffffffu, rs1, 2);
            l0 = l0 * al0 + rs0;
            l1 = l1 * al1 + rs1;

            // scale O by alpha (known fragment layout: rows r0 / r0+8)
#pragma unroll
            for (int d = 0; d < 8; d++) {
                o[d][0] *= al0; o[d][1] *= al0;
                o[d][2] *= al1; o[d][3] *= al1;
            }
        }
        __syncwarp();

        if (active) {
            // ---- O += P3 * V3 (K=192) ----
#pragma unroll
            for (int kk = 0; kk < 12; kk++) {
                uint32_t pa[4];
                ldsm4(pa, psb + (uint32_t)((a_row * SQ + kk * 16 + a_col8) * 2));
#pragma unroll
                for (int np = 0; np < 4; np++) {
                    uint32_t vb[4];
                    ldsm4t(vb, vst + (uint32_t)(((kk * 16 + v_rowk) * SV +
                                                 np * 16 + v_col8) * 2));
                    mma16816(o[2 * np], pa, vb);
                    mma16816(o[2 * np + 1], pa, vb + 2);
                }
            }
        }
    }

    // ---- epilogue: write att3 directly (pattern a: hi,lo,hi) ----
    {
        const int b = bh >> 4;
        const int h = bh & 15;
        const float inv0 = 1.f / l0;
        const float inv1 = 1.f / l1;
        char* orow0 = (char*)ATT3 + (size_t)(b * NN + grow0) * (K3 * 2) +
                      (h * 192 + 6 * cq) * 2;
        char* orow1 = orow0 + (size_t)8 * (K3 * 2);
#pragma unroll
        for (int d = 0; d < 8; d++) {
            const float e00 = o[d][0] * inv0;
            const float e01 = o[d][1] * inv0;
            const float e10 = o[d][2] * inv1;
            const float e11 = o[d][3] * inv1;
            const __nv_bfloat16 h00 = __float2bfloat16(e00);
            const __nv_bfloat16 g00 = __float2bfloat16(e00 - __bfloat162float(h00));
            const __nv_bfloat16 h01 = __float2bfloat16(e01);
            const __nv_bfloat16 g01 = __float2bfloat16(e01 - __bfloat162float(h01));
            const __nv_bfloat16 h10 = __float2bfloat16(e10);
            const __nv_bfloat16 g10 = __float2bfloat16(e10 - __bfloat162float(h10));
            const __nv_bfloat16 h11 = __float2bfloat16(e11);
            const __nv_bfloat16 g11 = __float2bfloat16(e11 - __bfloat162float(h11));
            uint32_t* w0 = (uint32_t*)(orow0 + 48 * d);
            w0[0] = bfpack(h00, g00);
            w0[1] = bfpack(h00, h01);
            w0[2] = bfpack(g01, h01);
            uint32_t* w1 = (uint32_t*)(orow1 + 48 * d);
            w1[0] = bfpack(h10, g10);
            w1[1] = bfpack(h10, h11);
            w1[2] = bfpack(g11, h11);
        }
    }
}

// ---------------- launch ----------------
extern "C" void kernel_launch(void* const* d_in, const int* in_sizes, int n_in,
                              void* d_out, int out_size)
{
    const float* x            = (const float*)d_in[0];
    const float* rope         = (const float*)d_in[2];
    const float* Wqkv         = (const float*)d_in[3];
    const float* Wout         = (const float*)d_in[4];
    const float* bout         = (const float*)d_in[5];
    float* out = (float*)d_out;

    float *qkv;
    __nv_bfloat16 *q3, *k3, *v3, *x3, *wqkv3, *att3, *wout3;
    cudaGetSymbolAddress((void**)&qkv, g_qkv);
    cudaGetSymbolAddress((void**)&q3,  g_q3);
    cudaGetSymbolAddress((void**)&k3,  g_k3);
    cudaGetSymbolAddress((void**)&v3,  g_v3);
    cudaGetSymbolAddress((void**)&x3,    g_x3);
    cudaGetSymbolAddress((void**)&wqkv3, g_wqkv3);
    cudaGetSymbolAddress((void**)&att3,  g_att3);
    cudaGetSymbolAddress((void**)&wout3, g_wout3);

    cudaFuncSetAttribute(gemm_bf16_nt, cudaFuncAttributeMaxDynamicSharedMemorySize,
                         GEMM_SMEM);
    cudaFuncSetAttribute(flash_mma, cudaFuncAttributeMaxDynamicSharedMemorySize,
                         FLASH_SMEM);

    // splits (x and both weight matrices)
    split3_a<<<(MROWS * DD / 8 + 255) / 256, 256>>>(x, x3, MROWS * DD / 8);
    split3_b<<<(QKVC * DD / 8 + 255) / 256, 256>>>(Wqkv, wqkv3, QKVC * DD / 8);
    split3_b<<<(DD * DD / 8 + 255) / 256, 256>>>(Wout, wout3, DD * DD / 8);

    // 1) qkv = x @ Wqkv^T
    gemm_bf16_nt<<<dim3(QKVC / 128, MROWS / 128), 256, GEMM_SMEM>>>(
        x3, wqkv3, qkv, MROWS, QKVC, K3);

    // 2) RoPE + split -> Q3, K3, V3
    rope3_kernel<<<(BB * NN * HH * 32 + 255) / 256, 256>>>(qkv, rope, q3, k3, v3);

    // 3) causal flash attention -> att3 (pre-split for out-proj)
    flash_mma<<<dim3(NN / 128, BB * HH), 256, FLASH_SMEM>>>(q3, k3, v3, att3);

    // 4) out = att @ Wout^T + bias
    gemm_bf16_nt<<<dim3(OUTC / 128, MROWS / 128), 256, GEMM_SMEM>>>(
        att3, wout3, out, MROWS, OUTC, K3);
    bias_add<<<(MROWS * OUTC / 4 + 255) / 256, 256>>>(
        out, bout, MROWS * OUTC / 4, OUTC);
}

// round 11
// speedup vs baseline: 1.4951x; 1.1133x over previous
#include <cuda_runtime.h>
#include <cuda_bf16.h>
#include <cuda_pipeline.h>
#include <float.h>
#include <math.h>
#include <stdint.h>

// Problem constants
#define BB 2
#define NN 2048
#define DD 1024
#define HH 16
#define DH 64
#define DH3 (3*DH)           // 192
#define MROWS (BB*NN)        // 4096
#define QKVC (3*HH*DH)       // 3072
#define OUTC (HH*DH)         // 1024
#define K3 (3*DD)            // 3072

// GEMM tile config (raw mma, 3-stage pipeline)
#define GST 72               // smem row stride (elems), 144B
#define TSZ (128 * GST)      // one 128x64 tile (padded) elems = 9216
#define GS_STAGE (2 * TSZ)   // A+B per stage elems = 18432
#define GEMM_SMEM (3 * GS_STAGE * 2)   // 110592 bytes

// Flash config: BM=128 q rows, BN=64 kv cols, 8 warps, register accumulators.
#define SQ 200               // q/k/p smem row stride (elems): 400B
#define SV 72                // v smem row stride: 144B
#define FOFF_K 51200         // q3s: 128*200*2
#define FOFF_V 102400        // k3s: 2*64*200*2
#define FOFF_P 157696        // v3s: 2*192*72*2
#define FLASH_SMEM 208896    // + p3s: 128*200*2
#define KSTAGE (64 * SQ)     // elems
#define VSTAGE (192 * SV)

// ---------------- scratch ----------------
__device__ __align__(16) float g_qkv[(size_t)MROWS * QKVC];
__device__ __align__(16) __nv_bfloat16 g_q3[(size_t)BB * HH * NN * DH3];
__device__ __align__(16) __nv_bfloat16 g_k3[(size_t)BB * HH * NN * DH3];
__device__ __align__(16) __nv_bfloat16 g_v3[(size_t)BB * HH * 3 * NN * DH];
__device__ __align__(16) __nv_bfloat16 g_x3[(size_t)MROWS * K3];
__device__ __align__(16) __nv_bfloat16 g_wqkv3[(size_t)QKVC * K3];
__device__ __align__(16) __nv_bfloat16 g_att3[(size_t)MROWS * K3];
__device__ __align__(16) __nv_bfloat16 g_wout3[(size_t)DD * K3];

// ---------------- helpers ----------------
__device__ __forceinline__ uint32_t bfpack(__nv_bfloat16 a, __nv_bfloat16 b) {
    __nv_bfloat162 t;
    t.x = a; t.y = b;
    return *(uint32_t*)&t;
}

// Fast exp2 on FMA/ALU pipes (no MUFU). rel err ~2e-6.
__device__ __forceinline__ float exp2_fast(float t) {
    t = fmaxf(t, -126.0f);
    const float fi = t + 12582912.0f;
    const float r = t - (fi - 12582912.0f);
    float p = 1.3333558e-3f;
    p = fmaf(p, r, 9.6181291e-3f);
    p = fmaf(p, r, 5.5504109e-2f);
    p = fmaf(p, r, 2.4022651e-1f);
    p = fmaf(p, r, 6.9314718e-1f);
    p = fmaf(p, r, 1.0f);
    const int ib = __float_as_int(fi) - 0x4B400000;
    return __int_as_float(__float_as_int(p) + (ib << 23));
}

// Raw MMA / ldmatrix wrappers. Brace characters in the PTX strings are written
// as octal escapes so the source contains no literal braces inside strings.
__device__ __forceinline__ void mma16816(float* d, const uint32_t* a, const uint32_t* b) {
    asm volatile(
        "mma.sync.aligned.m16n8k16.row.col.f32.bf16.bf16.f32 "
        "\173%0,%1,%2,%3\175,\173%4,%5,%6,%7\175,\173%8,%9\175,\173%0,%1,%2,%3\175;"
        : "+f"(d[0]), "+f"(d[1]), "+f"(d[2]), "+f"(d[3])
        : "r"(a[0]), "r"(a[1]), "r"(a[2]), "r"(a[3]), "r"(b[0]), "r"(b[1]));
}
__device__ __forceinline__ void ldsm4(uint32_t* r, uint32_t addr) {
    asm volatile(
        "ldmatrix.sync.aligned.m8n8.x4.shared.b16 \173%0,%1,%2,%3\175,[%4];"
        : "=r"(r[0]), "=r"(r[1]), "=r"(r[2]), "=r"(r[3]) : "r"(addr));
}
__device__ __forceinline__ void ldsm4t(uint32_t* r, uint32_t addr) {
    asm volatile(
        "ldmatrix.sync.aligned.m8n8.x4.trans.shared.b16 \173%0,%1,%2,%3\175,[%4];"
        : "=r"(r[0]), "=r"(r[1]), "=r"(r[2]), "=r"(r[3]) : "r"(addr));
}

// ---------------- bf16 3-way split kernels ----------------
__global__ void __launch_bounds__(256)
split3_a(const float* __restrict__ X, __nv_bfloat16* __restrict__ Y, int n8)
{
    const int i = blockIdx.x * 256 + threadIdx.x;
    if (i >= n8) return;
    float f[8];
    *(float4*)&f[0] = *(const float4*)(X + (size_t)i * 8);
    *(float4*)&f[4] = *(const float4*)(X + (size_t)i * 8 + 4);
    __nv_bfloat16 o[24];
#pragma unroll
    for (int j = 0; j < 8; j++) {
        const __nv_bfloat16 hi = __float2bfloat16(f[j]);
        const __nv_bfloat16 lo = __float2bfloat16(f[j] - __bfloat162float(hi));
        o[3*j] = hi; o[3*j+1] = lo; o[3*j+2] = hi;
    }
    uint4* dst = (uint4*)(Y + (size_t)i * 24);
    const uint4* src = (const uint4*)o;
    dst[0] = src[0]; dst[1] = src[1]; dst[2] = src[2];
}

__global__ void __launch_bounds__(256)
split3_b(const float* __restrict__ X, __nv_bfloat16* __restrict__ Y, int n8)
{
    const int i = blockIdx.x * 256 + threadIdx.x;
    if (i >= n8) return;
    float f[8];
    *(float4*)&f[0] = *(const float4*)(X + (size_t)i * 8);
    *(float4*)&f[4] = *(const float4*)(X + (size_t)i * 8 + 4);
    __nv_bfloat16 o[24];
#pragma unroll
    for (int j = 0; j < 8; j++) {
        const __nv_bfloat16 hi = __float2bfloat16(f[j]);
        const __nv_bfloat16 lo = __float2bfloat16(f[j] - __bfloat162float(hi));
        o[3*j] = hi; o[3*j+1] = hi; o[3*j+2] = lo;
    }
    uint4* dst = (uint4*)(Y + (size_t)i * 24);
    const uint4* src = (const uint4*)o;
    dst[0] = src[0]; dst[1] = src[1]; dst[2] = src[2];
}

// ---------------- GEMM stage loader (one 128x64 A tile + B tile) -----------
__device__ __forceinline__ void gemm_load_stage(
    __nv_bfloat16* s, const __nv_bfloat16* A, const __nv_bfloat16* B,
    int m0, int n0, int k0, int K, int tid)
{
#pragma unroll
    for (int p = 0; p < 8; p++) {
        const int c = tid + p * 256;
        const int row = (c >> 3) & 127;
        const int ch = c & 7;
        if (p < 4) {
            __pipeline_memcpy_async(s + row * GST + ch * 8,
                                    A + (size_t)(m0 + row) * K + k0 + ch * 8, 16);
        } else {
            __pipeline_memcpy_async(s + TSZ + row * GST + ch * 8,
                                    B + (size_t)(n0 + row) * K + k0 + ch * 8, 16);
        }
    }
    __pipeline_commit();
}

// ---------------- raw-mma GEMM: C = A3 * B3^T (+bias) ----------------------
// 128x128 block, BK=64, 8 warps (2x4), warp tile 64x32, 3-stage pipeline,
// ONE __syncthreads per k-iteration.
__global__ void __launch_bounds__(256, 2)
gemm_mma_nt(const __nv_bfloat16* __restrict__ A, const __nv_bfloat16* __restrict__ B,
            const float* __restrict__ bias, float* __restrict__ C,
            int M, int N, int K)
{
    extern __shared__ __nv_bfloat16 smem[];

    const int tid = threadIdx.x;
    const int lane = tid & 31;
    const int w = tid >> 5;
    const int wm = (w >> 2) * 64;
    const int wn = (w & 3) * 32;
    const int m0 = blockIdx.y * 128;
    const int n0 = blockIdx.x * 128;
    const int ntiles = K / 64;

    const uint32_t sb = (uint32_t)__cvta_generic_to_shared(smem);

    float acc[4][4][4];
#pragma unroll
    for (int mi = 0; mi < 4; mi++)
#pragma unroll
        for (int n8 = 0; n8 < 4; n8++)
#pragma unroll
            for (int e = 0; e < 4; e++) acc[mi][n8][e] = 0.f;

    // prologue: stages 0 and 1
    gemm_load_stage(smem, A, B, m0, n0, 0, K, tid);
    gemm_load_stage(smem + GS_STAGE, A, B, m0, n0, 64, K, tid);

    // ldmatrix lane addressing (validated in flash kernel)
    const int a_r = lane & 15;
    const int a_c8 = (lane >> 4) * 8;
    const int b_r = ((lane >> 4) << 3) + (lane & 7);
    const int b_c8 = ((lane >> 3) & 1) * 8;

    for (int kt = 0; kt < ntiles; kt++) {
        if (kt + 1 < ntiles) __pipeline_wait_prior(1);
        else                 __pipeline_wait_prior(0);
        __syncthreads();
        if (kt + 2 < ntiles)
            gemm_load_stage(smem + ((kt + 2) % 3) * GS_STAGE, A, B, m0, n0,
                            (kt + 2) * 64, K, tid);

        const uint32_t asb = sb + (uint32_t)((kt % 3) * GS_STAGE * 2);
        const uint32_t bsb = asb + (uint32_t)(TSZ * 2);
#pragma unroll
        for (int kk = 0; kk < 4; kk++) {
            uint32_t a[4][4];
            uint32_t b[2][4];
#pragma unroll
            for (int mi = 0; mi < 4; mi++)
                ldsm4(a[mi], asb + (uint32_t)(((wm + mi * 16 + a_r) * GST +
                                               kk * 16 + a_c8) * 2));
#pragma unroll
            for (int ni = 0; ni < 2; ni++)
                ldsm4(b[ni], bsb + (uint32_t)(((wn + ni * 16 + b_r) * GST +
                                               kk * 16 + b_c8) * 2));
#pragma unroll
            for (int mi = 0; mi < 4; mi++)
#pragma unroll
                for (int ni = 0; ni < 2; ni++) {
                    mma16816(acc[mi][2 * ni], a[mi], b[ni]);
                    mma16816(acc[mi][2 * ni + 1], a[mi], b[ni] + 2);
                }
        }
    }

    // epilogue (+ optional bias)
    const int r0 = lane >> 2;
    const int c0 = 2 * (lane & 3);
#pragma unroll
    for (int mi = 0; mi < 4; mi++) {
#pragma unroll
        for (int n8 = 0; n8 < 4; n8++) {
            const int row = m0 + wm + mi * 16 + r0;
            const int col = n0 + wn + n8 * 8 + c0;
            float b0 = 0.f, b1 = 0.f;
            if (bias) { b0 = bias[col]; b1 = bias[col + 1]; }
            *(float2*)(C + (size_t)row * N + col) =
                make_float2(acc[mi][n8][0] + b0, acc[mi][n8][1] + b1);
            *(float2*)(C + (size_t)(row + 8) * N + col) =
                make_float2(acc[mi][n8][2] + b0, acc[mi][n8][3] + b1);
        }
    }
}

// ---------------- RoPE + split: Q3/K3 [bh,N,192], V3 [bh,3N,64] ------------
__global__ void __launch_bounds__(256)
rope3_kernel(const float* __restrict__ qkv, const float* __restrict__ rope,
             __nv_bfloat16* __restrict__ Q3, __nv_bfloat16* __restrict__ K3g,
             __nv_bfloat16* __restrict__ V3)
{
    const int idx = blockIdx.x * 256 + threadIdx.x;
    if (idx >= BB * NN * HH * 32) return;
    const int p2 = (idx & 31) << 1;
    const int h  = (idx >> 5) & (HH - 1);
    const int n  = (idx >> 9) & (NN - 1);
    const int b  = idx >> 20;

    const float f0 = rope[n * DH + p2];
    const float f1 = rope[n * DH + p2 + 1];
    float s0, c0, s1, c1;
    sincosf(f0, &s0, &c0);
    sincosf(f1, &s1, &c1);

    const size_t row = ((size_t)b * NN + n) * QKVC;
    const float2 q = *(const float2*)(qkv + row + h * DH + p2);
    const float2 k = *(const float2*)(qkv + row + OUTC + h * DH + p2);
    const float2 v = *(const float2*)(qkv + row + 2 * OUTC + h * DH + p2);

    const float SCALE = 0.125f;
    float qx = (q.x * c0 - q.y * s0) * SCALE;
    float qy = (q.y * c1 + q.x * s1) * SCALE;
    float kx = k.x * c0 - k.y * s0;
    float ky = k.y * c1 + k.x * s1;
    float vx = v.x * c0 - v.y * s0;
    float vy = v.y * c1 + v.x * s1;

    const __nv_bfloat16 qh0 = __float2bfloat16(qx);
    const __nv_bfloat16 ql0 = __float2bfloat16(qx - __bfloat162float(qh0));
    const __nv_bfloat16 qh1 = __float2bfloat16(qy);
    const __nv_bfloat16 ql1 = __float2bfloat16(qy - __bfloat162float(qh1));
    const __nv_bfloat16 kh0 = __float2bfloat16(kx);
    const __nv_bfloat16 kl0 = __float2bfloat16(kx - __bfloat162float(kh0));
    const __nv_bfloat16 kh1 = __float2bfloat16(ky);
    const __nv_bfloat16 kl1 = __float2bfloat16(ky - __bfloat162float(kh1));
    const __nv_bfloat16 vh0 = __float2bfloat16(vx);
    const __nv_bfloat16 vl0 = __float2bfloat16(vx - __bfloat162float(vh0));
    const __nv_bfloat16 vh1 = __float2bfloat16(vy);
    const __nv_bfloat16 vl1 = __float2bfloat16(vy - __bfloat162float(vh1));

    const int bh = b * HH + h;
    uint32_t* qp = (uint32_t*)(Q3 + ((size_t)bh * NN + n) * DH3 + 3 * p2);
    qp[0] = bfpack(qh0, ql0);
    qp[1] = bfpack(qh0, qh1);
    qp[2] = bfpack(ql1, qh1);
    uint32_t* kp = (uint32_t*)(K3g + ((size_t)bh * NN + n) * DH3 + 3 * p2);
    kp[0] = bfpack(kh0, kh0);
    kp[1] = bfpack(kl0, kh1);
    kp[2] = bfpack(kh1, kl1);
    uint32_t* vp = (uint32_t*)(V3 + ((size_t)bh * 3 * NN + 3 * n) * DH + p2);
    const uint32_t vhi = bfpack(vh0, vh1);
    vp[0] = vhi;
    vp[DH / 2] = vhi;
    vp[DH] = bfpack(vl0, vl1);
}

// ---------------- flash K/V stage prefetch (BN=64) ----------------
__device__ __forceinline__ void flash_prefetch(
    __nv_bfloat16* ks, __nv_bfloat16* vsm,
    const __nv_bfloat16* Kbase, const __nv_bfloat16* Vbase,
    int kv0, int tid)
{
#pragma unroll
    for (int p = 0; p < 6; p++) {
        const int c = tid + p * 256;
        const int r = c / 24;
        const int col = (c % 24) * 8;
        __pipeline_memcpy_async(ks + r * SQ + col,
                                Kbase + (size_t)(kv0 + r) * DH3 + col, 16);
    }
#pragma unroll
    for (int p = 0; p < 6; p++) {
        const int c = tid + p * 256;
        const int r = c >> 3;
        const int col = (c & 7) * 8;
        __pipeline_memcpy_async(vsm + r * SV + col,
                                Vbase + (size_t)(3 * kv0 + r) * DH + col, 16);
    }
    __pipeline_commit();
}

// ---------------- Flash attention: register mma, BM=128, BN=64 -------------
__global__ void __launch_bounds__(256)
flash_mma(const __nv_bfloat16* __restrict__ Q3,
          const __nv_bfloat16* __restrict__ Kg3,
          const __nv_bfloat16* __restrict__ Vg3,
          __nv_bfloat16* __restrict__ ATT3)
{
    extern __shared__ char fsm[];
    __nv_bfloat16* q3s = (__nv_bfloat16*)fsm;
    __nv_bfloat16* k3s = (__nv_bfloat16*)(fsm + FOFF_K);
    __nv_bfloat16* v3s = (__nv_bfloat16*)(fsm + FOFF_V);
    __nv_bfloat16* p3s = (__nv_bfloat16*)(fsm + FOFF_P);

    const int tid = threadIdx.x;
    const int w = tid >> 5;
    const int lane = tid & 31;
    const int qt = blockIdx.x;
    const int bh = blockIdx.y;
    const int q0 = qt * 128;

    const __nv_bfloat16* Qbase = Q3 + ((size_t)bh * NN + q0) * DH3;
    const __nv_bfloat16* Kbase = Kg3 + (size_t)bh * NN * DH3;
    const __nv_bfloat16* Vbase = Vg3 + (size_t)bh * 3 * NN * DH;

    const uint32_t qsb = (uint32_t)__cvta_generic_to_shared(q3s);
    const uint32_t ksb = (uint32_t)__cvta_generic_to_shared(k3s);
    const uint32_t vsb = (uint32_t)__cvta_generic_to_shared(v3s);
    const uint32_t psb = (uint32_t)__cvta_generic_to_shared(p3s);

    flash_prefetch(k3s, v3s, Kbase, Vbase, 0, tid);

#pragma unroll
    for (int p = 0; p < 12; p++) {
        const int c = tid + p * 256;
        const int r = c / 24;
        const int col = (c % 24) * 8;
        *(uint4*)(q3s + r * SQ + col) =
            *(const uint4*)(Qbase + (size_t)r * DH3 + col);
    }

    const int r0 = lane >> 2;
    const int cq = lane & 3;
    const int mrow = 16 * w;
    const int grow0 = q0 + mrow + r0;
    const int grow1 = grow0 + 8;

    const int a_row = mrow + (lane & 15);
    const int a_col8 = (lane >> 4) * 8;
    const int b_rowk = ((lane >> 4) << 3) + (lane & 7);
    const int b_colk8 = ((lane >> 3) & 1) * 8;
    const int v_rowk = lane & 15;
    const int v_col8 = (lane >> 4) * 8;

    float o[8][4];
#pragma unroll
    for (int d = 0; d < 8; d++)
#pragma unroll
        for (int e = 0; e < 4; e++) o[d][e] = 0.f;
    float m0 = -1e30f, m1 = -1e30f, l0 = 0.f, l1 = 0.f;

    const int last = 2 * qt + 1;
    for (int kt = 0; kt <= last; kt++) {
        const int st = kt & 1;
        const int kv0 = kt * 64;

        __pipeline_wait_prior(0);
        __syncthreads();
        if (kt < last)
            flash_prefetch(k3s + (st ^ 1) * KSTAGE, v3s + (st ^ 1) * VSTAGE,
                           Kbase, Vbase, kv0 + 64, tid);

        const bool active = (kv0 <= q0 + mrow + 15);
        const uint32_t kst = ksb + (uint32_t)(st * KSTAGE * 2);
        const uint32_t vst = vsb + (uint32_t)(st * VSTAGE * 2);

        if (active) {
            float sacc[8][4];
#pragma unroll
            for (int d = 0; d < 8; d++)
#pragma unroll
                for (int e = 0; e < 4; e++) sacc[d][e] = 0.f;

#pragma unroll
            for (int kk = 0; kk < 12; kk++) {
                uint32_t a[4];
                ldsm4(a, qsb + (uint32_t)((a_row * SQ + kk * 16 + a_col8) * 2));
#pragma unroll
                for (int np = 0; np < 4; np++) {
                    uint32_t b[4];
                    ldsm4(b, kst + (uint32_t)(((np * 16 + b_rowk) * SQ +
                                               kk * 16 + b_colk8) * 2));
                    mma16816(sacc[2 * np], a, b);
                    mma16816(sacc[2 * np + 1], a, b + 2);
                }
            }

            if (kv0 + 63 > grow0) {
#pragma unroll
                for (int d = 0; d < 8; d++) {
                    const int col = kv0 + d * 8 + 2 * cq;
                    if (col > grow0)     sacc[d][0] = -1e30f;
                    if (col + 1 > grow0) sacc[d][1] = -1e30f;
                    if (col > grow1)     sacc[d][2] = -1e30f;
                    if (col + 1 > grow1) sacc[d][3] = -1e30f;
                }
            }
            float rm0 = sacc[0][0], rm1 = sacc[0][2];
#pragma unroll
            for (int d = 0; d < 8; d++) {
                rm0 = fmaxf(rm0, fmaxf(sacc[d][0], sacc[d][1]));
                rm1 = fmaxf(rm1, fmaxf(sacc[d][2], sacc[d][3]));
            }
            rm0 = fmaxf(rm0, __shfl_xor_sync(0xffffffffu, rm0, 1));
            rm0 = fmaxf(rm0, __shfl_xor_sync(0xffffffffu, rm0, 2));
            rm1 = fmaxf(rm1, __shfl_xor_sync(0xffffffffu, rm1, 1));
            rm1 = fmaxf(rm1, __shfl_xor_sync(0xffffffffu, rm1, 2));
            const float mn0 = fmaxf(m0, rm0);
            const float mn1 = fmaxf(m1, rm1);
            const float al0 = exp2_fast((m0 - mn0) * 1.4426950f);
            const float al1 = exp2_fast((m1 - mn1) * 1.4426950f);
            m0 = mn0; m1 = mn1;

            float rs0 = 0.f, rs1 = 0.f;
            char* prow0 = (char*)p3s + (mrow + r0) * (SQ * 2) + 12 * cq;
            char* prow1 = prow0 + 8 * (SQ * 2);
#pragma unroll
            for (int d = 0; d < 8; d++) {
                const float p00 = exp2_fast((sacc[d][0] - mn0) * 1.4426950f);
                const float p01 = exp2_fast((sacc[d][1] - mn0) * 1.4426950f);
                const float p10 = exp2_fast((sacc[d][2] - mn1) * 1.4426950f);
                const float p11 = exp2_fast((sacc[d][3] - mn1) * 1.4426950f);
                rs0 += p00 + p01;
                rs1 += p10 + p11;
                const __nv_bfloat16 h00 = __float2bfloat16(p00);
                const __nv_bfloat16 g00 = __float2bfloat16(p00 - __bfloat162float(h00));
                const __nv_bfloat16 h01 = __float2bfloat16(p01);
                const __nv_bfloat16 g01 = __float2bfloat16(p01 - __bfloat162float(h01));
                const __nv_bfloat16 h10 = __float2bfloat16(p10);
                const __nv_bfloat16 g10 = __float2bfloat16(p10 - __bfloat162float(h10));
                const __nv_bfloat16 h11 = __float2bfloat16(p11);
                const __nv_bfloat16 g11 = __float2bfloat16(p11 - __bfloat162float(h11));
                uint32_t* w0 = (uint32_t*)(prow0 + 48 * d);
                w0[0] = bfpack(h00, g00);
                w0[1] = bfpack(h00, h01);
                w0[2] = bfpack(g01, h01);
                uint32_t* w1 = (uint32_t*)(prow1 + 48 * d);
                w1[0] = bfpack(h10, g10);
                w1[1] = bfpack(h10, h11);
                w1[2] = bfpack(g11, h11);
            }
            rs0 += __shfl_xor_sync(0xffffffffu, rs0, 1);
            rs0 += __shfl_xor_sync(0xffffffffu, rs0, 2);
            rs1 += __shfl_xor_sync(0xffffffffu, rs1, 1);
            rs1 += __shfl_xor_sync(0xffffffffu, rs1, 2);
            l0 = l0 * al0 + rs0;
            l1 = l1 * al1 + rs1;

#pragma unroll
            for (int d = 0; d < 8; d++) {
                o[d][0] *= al0; o[d][1] *= al0;
                o[d][2] *= al1; o[d][3] *= al1;
            }
        }
        __syncwarp();

        if (active) {
#pragma unroll
            for (int kk = 0; kk < 12; kk++) {
                uint32_t pa[4];
                ldsm4(pa, psb + (uint32_t)((a_row * SQ + kk * 16 + a_col8) * 2));
#pragma unroll
                for (int np = 0; np < 4; np++) {
                    uint32_t vb[4];
                    ldsm4t(vb, vst + (uint32_t)(((kk * 16 + v_rowk) * SV +
                                                 np * 16 + v_col8) * 2));
                    mma16816(o[2 * np], pa, vb);
                    mma16816(o[2 * np + 1], pa, vb + 2);
                }
            }
        }
    }

    // epilogue: write att3 directly (pattern a: hi,lo,hi)
    {
        const int b = bh >> 4;
        const int h = bh & 15;
        const float inv0 = 1.f / l0;
        const float inv1 = 1.f / l1;
        char* orow0 = (char*)ATT3 + (size_t)(b * NN + grow0) * (K3 * 2) +
                      (h * 192 + 6 * cq) * 2;
        char* orow1 = orow0 + (size_t)8 * (K3 * 2);
#pragma unroll
        for (int d = 0; d < 8; d++) {
            const float e00 = o[d][0] * inv0;
            const float e01 = o[d][1] * inv0;
            const float e10 = o[d][2] * inv1;
            const float e11 = o[d][3] * inv1;
            const __nv_bfloat16 h00 = __float2bfloat16(e00);
            const __nv_bfloat16 g00 = __float2bfloat16(e00 - __bfloat162float(h00));
            const __nv_bfloat16 h01 = __float2bfloat16(e01);
            const __nv_bfloat16 g01 = __float2bfloat16(e01 - __bfloat162float(h01));
            const __nv_bfloat16 h10 = __float2bfloat16(e10);
            const __nv_bfloat16 g10 = __float2bfloat16(e10 - __bfloat162float(h10));
            const __nv_bfloat16 h11 = __float2bfloat16(e11);
            const __nv_bfloat16 g11 = __float2bfloat16(e11 - __bfloat162float(h11));
            uint32_t* w0 = (uint32_t*)(orow0 + 48 * d);
            w0[0] = bfpack(h00, g00);
            w0[1] = bfpack(h00, h01);
            w0[2] = bfpack(g01, h01);
            uint32_t* w1 = (uint32_t*)(orow1 + 48 * d);
            w1[0] = bfpack(h10, g10);
            w1[1] = bfpack(h10, h11);
            w1[2] = bfpack(g11, h11);
        }
    }
}

// ---------------- launch ----------------
extern "C" void kernel_launch(void* const* d_in, const int* in_sizes, int n_in,
                              void* d_out, int out_size)
{
    const float* x            = (const float*)d_in[0];
    const float* rope         = (const float*)d_in[2];
    const float* Wqkv         = (const float*)d_in[3];
    const float* Wout         = (const float*)d_in[4];
    const float* bout         = (const float*)d_in[5];
    float* out = (float*)d_out;

    float *qkv;
    __nv_bfloat16 *q3, *k3, *v3, *x3, *wqkv3, *att3, *wout3;
    cudaGetSymbolAddress((void**)&qkv, g_qkv);
    cudaGetSymbolAddress((void**)&q3,  g_q3);
    cudaGetSymbolAddress((void**)&k3,  g_k3);
    cudaGetSymbolAddress((void**)&v3,  g_v3);
    cudaGetSymbolAddress((void**)&x3,    g_x3);
    cudaGetSymbolAddress((void**)&wqkv3, g_wqkv3);
    cudaGetSymbolAddress((void**)&att3,  g_att3);
    cudaGetSymbolAddress((void**)&wout3, g_wout3);

    cudaFuncSetAttribute(gemm_mma_nt, cudaFuncAttributeMaxDynamicSharedMemorySize,
                         GEMM_SMEM);
    cudaFuncSetAttribute(flash_mma, cudaFuncAttributeMaxDynamicSharedMemorySize,
                         FLASH_SMEM);

    // splits (x and both weight matrices)
    split3_a<<<(MROWS * DD / 8 + 255) / 256, 256>>>(x, x3, MROWS * DD / 8);
    split3_b<<<(QKVC * DD / 8 + 255) / 256, 256>>>(Wqkv, wqkv3, QKVC * DD / 8);
    split3_b<<<(DD * DD / 8 + 255) / 256, 256>>>(Wout, wout3, DD * DD / 8);

    // 1) qkv = x @ Wqkv^T
    gemm_mma_nt<<<dim3(QKVC / 128, MROWS / 128), 256, GEMM_SMEM>>>(
        x3, wqkv3, (const float*)0, qkv, MROWS, QKVC, K3);

    // 2) RoPE + split -> Q3, K3, V3
    rope3_kernel<<<(BB * NN * HH * 32 + 255) / 256, 256>>>(qkv, rope, q3, k3, v3);

    // 3) causal flash attention -> att3 (pre-split for out-proj)
    flash_mma<<<dim3(NN / 128, BB * HH), 256, FLASH_SMEM>>>(q3, k3, v3, att3);

    // 4) out = att @ Wout^T + bias (fused)
    gemm_mma_nt<<<dim3(OUTC / 128, MROWS / 128), 256, GEMM_SMEM>>>(
        att3, wout3, bout, out, MROWS, OUTC, K3);
}